// round 13
// baseline (speedup 1.0000x reference)
#include <cuda_runtime.h>
#include <cuda_bf16.h>
#include <cstdint>

// ---------------- problem constants ----------------
#define NB   8
#define HW   4096            // 64*64
#define DD   256
#define KKK  8192
#define NN   32768           // NB*HW
#define BM   128
#define BN   128
#define BK   64
#define NT_M 256             // NN/BM
#define NT_K 64              // KKK/BN
#define DELTA 5e-4f

// output layout: z_q_x at 0, z_q_x_bar at 8388608, logits at 16777216 (floats)
#define ZQ_ELEMS   8388608
#define LOGITS_OFF 16777216

// ---------------- device scratch (static, allowed) ----------------
__device__ __align__(16) __nv_bfloat16 g_xb[(size_t)NN * DD];   // 16MB x bf16 [N,D]
__device__ __align__(16) __nv_bfloat16 g_cbb[(size_t)KKK * DD]; //  4MB cb bf16 [K,D]
__device__ __align__(16) float g_xf[(size_t)NN * DD];           // 32MB x fp32 [N,D]
__device__ float g_xsqr[NN];
__device__ float g_cbsqr[KKK];
__device__ float g_blkmin[(size_t)NN * NT_K];                   // 8MB per-pixel per-block approx min dist
__device__ int   g_idx[NN];

// ---------------- PTX helpers (plain sm_103-legal only) ----------------
__device__ __forceinline__ uint32_t smem_u32(const void* p) {
    uint32_t a;
    asm("{ .reg .u64 t; cvta.to.shared.u64 t, %1; cvt.u32.u64 %0, t; }" : "=r"(a) : "l"(p));
    return a;
}
__device__ __forceinline__ void cp_async16(uint32_t dst, const void* src) {
    asm volatile("cp.async.cg.shared.global [%0], [%1], 16;" :: "r"(dst), "l"(src) : "memory");
}
#define CP_COMMIT() asm volatile("cp.async.commit_group;" ::: "memory")
#define CP_WAIT(n)  asm volatile("cp.async.wait_group %0;" :: "n"(n) : "memory")

__device__ __forceinline__ void ldsm_x4(uint32_t* d, uint32_t addr) {
    asm volatile("ldmatrix.sync.aligned.m8n8.x4.shared.b16 {%0,%1,%2,%3}, [%4];"
        : "=r"(d[0]), "=r"(d[1]), "=r"(d[2]), "=r"(d[3]) : "r"(addr));
}
__device__ __forceinline__ void mma16816(float* c, const uint32_t* a, uint32_t b0, uint32_t b1) {
    asm volatile(
        "mma.sync.aligned.m16n8k16.row.col.f32.bf16.bf16.f32 "
        "{%0,%1,%2,%3}, {%4,%5,%6,%7}, {%8,%9}, {%0,%1,%2,%3};"
        : "+f"(c[0]), "+f"(c[1]), "+f"(c[2]), "+f"(c[3])
        : "r"(a[0]), "r"(a[1]), "r"(a[2]), "r"(a[3]), "r"(b0), "r"(b1));
}

// ---------------- prep: codebook -> bf16 [K,256] + cb_sqr  (FIXED: full 256 cols) ----------------
__global__ void prep_cb_kernel(const float* __restrict__ cb) {
    __shared__ float s_rs[128];
    int t = threadIdx.x, blk = blockIdx.x;
    if (t < 128) s_rs[t] = 0.f;
    __syncthreads();
    int k0 = blk * 128;
    // 128 rows * 64 float4 chunks = 8192 items
    for (int j = 0; j < 32; j++) {
        int i = t + j * 256;
        int r = i >> 6, c = i & 63;
        float4 v = ((const float4*)(cb + (size_t)(k0 + r) * DD))[c];
        float sq = v.x * v.x + v.y * v.y + v.z * v.z + v.w * v.w;
        atomicAdd(&s_rs[r], sq);
        __nv_bfloat162 h0 = __floats2bfloat162_rn(v.x, v.y);
        __nv_bfloat162 h1 = __floats2bfloat162_rn(v.z, v.w);
        uint2 u;
        u.x = *(uint32_t*)&h0; u.y = *(uint32_t*)&h1;
        ((uint2*)(g_cbb + (size_t)(k0 + r) * DD))[c] = u;
    }
    __syncthreads();
    if (t < 128) g_cbsqr[k0 + t] = s_rs[t];
}

// ---------------- prep: x transpose -> bf16 [N,256] + fp32 [N,256] + x_sqr ----------------
#define PXB 528u
#define PXF 1040u
#define PX_SMEM (128 * 528 + 128 * 1040 + 512)
__global__ void prep_x_kernel(const float* __restrict__ z) {
    extern __shared__ unsigned char sm[];
    unsigned char* smh = sm;                  // bf16 tile, row stride 528
    unsigned char* smf = sm + 128 * PXB;      // fp32 tile, row stride 1040
    float* s_xs = (float*)(sm + 128 * PXB + 128 * PXF);
    int t = threadIdx.x, blk = blockIdx.x;
    if (t < 128) s_xs[t] = 0.f;
    __syncthreads();
    int b = blk >> 5, hw0 = (blk & 31) * 128;
    int nl = t & 127, dpar = t >> 7;
    const float* base = z + (size_t)b * DD * HW + hw0 + nl;
    float acc = 0.f;
    for (int d = dpar; d < DD; d += 2) {
        float v = base[(size_t)d * HW];
        acc += v * v;
        *(__nv_bfloat16*)(smh + nl * PXB + d * 2) = __float2bfloat16(v);
        *(float*)(smf + nl * PXF + d * 4) = v;
    }
    atomicAdd(&s_xs[nl], acc);
    __syncthreads();
    int n0 = blk * 128;
    if (t < 128) g_xsqr[n0 + t] = s_xs[t];
    for (int j = 0; j < 16; j++) {            // bf16 tile: 128 rows x 32 uint4
        int i = t + j * 256;
        int r = i >> 5, c = i & 31;
        uint4 v = *(const uint4*)(smh + r * PXB + c * 16);
        ((uint4*)(g_xb + (size_t)(n0 + r) * DD))[c] = v;
    }
    for (int j = 0; j < 32; j++) {            // f32 tile: 128 rows x 64 uint4
        int i = t + j * 256;
        int r = i >> 6, c = i & 63;
        uint4 v = *(const uint4*)(smf + r * PXF + c * 16);
        ((uint4*)(g_xf + (size_t)(n0 + r) * DD))[c] = v;
    }
}

// ---------------- main GEMM + fused epilogue (mma.sync bf16, ldmatrix + XOR swizzle) ----------------
#define GEMM_SMEM 68608

__global__ void __launch_bounds__(256, 2) gemm_kernel(float* __restrict__ out) {
    extern __shared__ unsigned char sm[];
    uint32_t smb = smem_u32(sm);
    float* stage = (float*)sm;                 // [col*132 + row]
    float* xs_s = (float*)(sm + 67584);
    float* cs_s = (float*)(sm + 68096);

    const int t = threadIdx.x;
    const int lane = t & 31, wid = t >> 5;
    const int warp_m = wid >> 2, warp_n = wid & 3;   // 2 x 4 warp grid
    const int mblk = blockIdx.y, nblk = blockIdx.x;
    const int m0 = mblk * BM, n0 = nblk * BN;

    if (t < 128) { xs_s[t] = g_xsqr[m0 + t]; cs_s[t] = g_cbsqr[n0 + t]; }

    float acc[4][4][4];
#pragma unroll
    for (int mf = 0; mf < 4; mf++)
#pragma unroll
        for (int nf = 0; nf < 4; nf++)
#pragma unroll
            for (int q = 0; q < 4; q++) acc[mf][nf][q] = 0.f;

    const __nv_bfloat16* gA = g_xb  + (size_t)m0 * DD;
    const __nv_bfloat16* gB = g_cbb + (size_t)n0 * DD;
#define ISSUE(s, kk) do {                                                        \
    uint32_t sa = smb + (s) * 16384;                                             \
    uint32_t sb = smb + 32768 + (s) * 16384;                                     \
    _Pragma("unroll")                                                            \
    for (int j = 0; j < 4; j++) {                                                \
        int i = t + j * 256;                                                     \
        int r = i >> 3, c = i & 7;                                               \
        uint32_t col = ((uint32_t)(c * 16)) ^ (((uint32_t)(r & 7)) << 4);        \
        cp_async16(sa + r * 128 + col, gA + (size_t)r * DD + (kk) * BK + c * 8); \
        cp_async16(sb + r * 128 + col, gB + (size_t)r * DD + (kk) * BK + c * 8); \
    }                                                                            \
    CP_COMMIT();                                                                 \
} while (0)

    ISSUE(0, 0);
    const int arow = lane & 15;
    const uint32_t cbase = ((uint32_t)((lane >> 4) * 16)); // 16B segment
    const uint32_t xm = ((uint32_t)(lane & 7)) << 4;       // swizzle mask (row&7)

#pragma unroll
    for (int kk = 0; kk < 4; kk++) {
        int s = kk & 1;
        if (kk < 3) { ISSUE(s ^ 1, kk + 1); CP_WAIT(1); }
        else        { CP_WAIT(0); }
        __syncthreads();
        uint32_t sa = smb + s * 16384;
        uint32_t sb = smb + 32768 + s * 16384;
#pragma unroll
        for (int ks = 0; ks < 4; ks++) {
            uint32_t colp = ((uint32_t)(ks * 32) + cbase) ^ xm;
            uint32_t a[4][4], b[4][2];
#pragma unroll
            for (int mf = 0; mf < 4; mf++) {
                int r = warp_m * 64 + mf * 16 + arow;
                ldsm_x4(a[mf], sa + r * 128 + colp);
            }
#pragma unroll
            for (int p = 0; p < 2; p++) {
                int r = warp_n * 32 + p * 16 + arow;
                uint32_t d[4];
                ldsm_x4(d, sb + r * 128 + colp);
                b[2 * p][0] = d[0]; b[2 * p + 1][0] = d[1];
                b[2 * p][1] = d[2]; b[2 * p + 1][1] = d[3];
            }
#pragma unroll
            for (int mf = 0; mf < 4; mf++)
#pragma unroll
                for (int nf = 0; nf < 4; nf++)
                    mma16816(acc[mf][nf], a[mf], b[nf][0], b[nf][1]);
        }
        __syncthreads();
    }

    // ---- epilogue: logit = 2*dot - xs - cs, transposed into smem ----
    int grp = lane >> 2, tid4 = lane & 3;
#pragma unroll
    for (int mf = 0; mf < 4; mf++) {
        int r = warp_m * 64 + mf * 16 + grp;
        float xs0 = xs_s[r], xs1 = xs_s[r + 8];
#pragma unroll
        for (int nf = 0; nf < 4; nf++) {
            int c = warp_n * 32 + nf * 8 + tid4 * 2;
            float cs0 = cs_s[c], cs1 = cs_s[c + 1];
            stage[c * 132 + r]           = 2.f * acc[mf][nf][0] - xs0 - cs0;
            stage[(c + 1) * 132 + r]     = 2.f * acc[mf][nf][1] - xs0 - cs1;
            stage[c * 132 + r + 8]       = 2.f * acc[mf][nf][2] - xs1 - cs0;
            stage[(c + 1) * 132 + r + 8] = 2.f * acc[mf][nf][3] - xs1 - cs1;
        }
    }
    __syncthreads();

    // ---- per-pixel block-local approx min distance ----
    {
        int r = t >> 1, half = t & 1;
        float bestv = 3.4e38f;
        for (int c = half * 64; c < half * 64 + 64; c++)
            bestv = fminf(bestv, -stage[c * 132 + r]);
        bestv = fminf(bestv, __shfl_xor_sync(0xFFFFFFFFu, bestv, 1));
        if (half == 0) g_blkmin[(size_t)(m0 + r) * NT_K + nblk] = bestv;
    }

    // ---- coalesced logit stores: one warp per code-column ----
    {
        int b = m0 >> 12;
        int hw0 = m0 & 4095;
        float* lg = out + (size_t)LOGITS_OFF + (size_t)b * KKK * HW + hw0;
#pragma unroll
        for (int it = 0; it < 16; it++) {
            int c = it * 8 + wid;
            float4 v = *(const float4*)&stage[c * 132 + lane * 4];
            *(float4*)(lg + (size_t)(n0 + c) * HW + lane * 4) = v;
        }
    }
}

// ---------------- exact argmin: shortlist from approx scores, fp64-exact rescore ----------------
// one warp per pixel; 8 warps per block
__global__ void __launch_bounds__(256) argmin_kernel(const float* __restrict__ cb,
                                                     const float* __restrict__ out) {
    int lane = threadIdx.x & 31;
    int p = blockIdx.x * 8 + (threadIdx.x >> 5);
    const float* bm = g_blkmin + (size_t)p * NT_K;
    float b0 = bm[lane], b1 = bm[32 + lane];
    float m = fminf(b0, b1);
#pragma unroll
    for (int o = 16; o; o >>= 1) m = fminf(m, __shfl_xor_sync(0xFFFFFFFFu, m, o));
    float thr = m + DELTA;

    int bq = p >> 12, hw = p & 4095;
    const float* lg = out + (size_t)LOGITS_OFF + (size_t)bq * KKK * HW + hw;

    // x row (fp32), 8 dims per lane
    float xr[8];
    {
        const float4* xrp = (const float4*)(g_xf + (size_t)p * DD) + lane * 2;
        *(float4*)(xr) = xrp[0];
        *(float4*)(xr + 4) = xrp[1];
    }
    float xs = g_xsqr[p];

    float bestd = 3.4e38f;
    int bestk = 0;
    unsigned q0 = __ballot_sync(0xFFFFFFFFu, b0 <= thr);
    unsigned q1 = __ballot_sync(0xFFFFFFFFu, b1 <= thr);
    for (int half = 0; half < 2; half++) {
        unsigned q = half ? q1 : q0;
        while (q) {
            int nb = __ffs(q) - 1; q &= q - 1;
            int k0 = (half * 32 + nb) * 128;
            for (int j = 0; j < 4; j++) {
                int k = k0 + j * 32 + lane;
                float da = -lg[(size_t)k * HW];
                unsigned cm = __ballot_sync(0xFFFFFFFFu, da <= thr);
                while (cm) {
                    int l = __ffs(cm) - 1; cm &= cm - 1;
                    int kc = k0 + j * 32 + l;
                    const float4* cp = (const float4*)(cb + (size_t)kc * DD) + lane * 2;
                    float4 c0 = cp[0], c1 = cp[1];
                    double s = (double)xr[0] * c0.x + (double)xr[1] * c0.y
                             + (double)xr[2] * c0.z + (double)xr[3] * c0.w
                             + (double)xr[4] * c1.x + (double)xr[5] * c1.y
                             + (double)xr[6] * c1.z + (double)xr[7] * c1.w;
#pragma unroll
                    for (int o = 16; o; o >>= 1) s += __shfl_xor_sync(0xFFFFFFFFu, s, o);
                    float m32 = (float)s;                 // correctly-rounded fp32 dot
                    float S = g_cbsqr[kc] + xs;           // replicate ref: fl(cs + xs)
                    float dist = S - 2.0f * m32;          // replicate ref rounding
                    if (dist < bestd) { bestd = dist; bestk = kc; }  // ascending k => first-min
                }
            }
        }
    }
    if (lane == 0) g_idx[p] = bestk;
}

// ---------------- gather: z_q_x / z_q_x_bar ----------------
__global__ void gather_kernel(const float* __restrict__ cb, float* __restrict__ out) {
    __shared__ int s_idx[128];
    int t = threadIdx.x, blk = blockIdx.x;
    if (t < 128) s_idx[t] = g_idx[blk * 128 + t];
    __syncthreads();
    int b = blk >> 5, hw0 = (blk & 31) * 128;
    int nl = t & 127, dpar = t >> 7;
    float* o1 = out + (size_t)b * DD * HW + hw0 + nl;
    float* o2 = o1 + ZQ_ELEMS;
    const float* row = cb + (size_t)s_idx[nl] * DD;
    for (int d = dpar; d < DD; d += 2) {
        float v = __ldg(row + d);
        o1[(size_t)d * HW] = v;
        o2[(size_t)d * HW] = v;
    }
}

// ---------------- launch ----------------
extern "C" void kernel_launch(void* const* d_in, const int* in_sizes, int n_in,
                              void* d_out, int out_size) {
    const float* z  = (const float*)d_in[0];   // z_e_x [8,256,64,64] f32
    const float* cb = (const float*)d_in[1];   // codebook [8192,256] f32
    float* out = (float*)d_out;

    cudaFuncSetAttribute(prep_x_kernel, cudaFuncAttributeMaxDynamicSharedMemorySize, PX_SMEM);
    cudaFuncSetAttribute(gemm_kernel,   cudaFuncAttributeMaxDynamicSharedMemorySize, GEMM_SMEM);

    prep_cb_kernel<<<NT_K, 256>>>(cb);
    prep_x_kernel<<<NT_M, 256, PX_SMEM>>>(z);
    dim3 grid(NT_K, NT_M);   // x = code-block (fast) so A tiles reuse L2
    gemm_kernel<<<grid, 256, GEMM_SMEM>>>(out);
    argmin_kernel<<<NN / 8, 256>>>(cb, out);
    gather_kernel<<<NT_M, 256>>>(cb, out);
}